// round 4
// baseline (speedup 1.0000x reference)
#include <cuda_runtime.h>

#define H  64
#define LL 2048
#define NB 256
#define NBLK 128         // 2 batches per block (one warp)
#define VOCAB 64
#define FULL 0xffffffffu

// -------- device-global scratch (no runtime allocation allowed) --------
__device__ __align__(16) float g_ktab[VOCAB * H];   // normalized k per vocab id
__device__ __align__(16) float g_vtab[VOCAB * H];   // v per vocab id
__device__ __align__(16) float g_qtab[VOCAB * H];   // q per vocab id
__device__ __align__(16) float g_KK[VOCAB * VOCAB]; // Gram of normalized k table
__device__ __align__(16) float g_Wcomb[H * H];      // Wout @ Wrp
__device__ __align__(16) float g_bcomb[H];          // Wout @ brp + bout

__device__ __forceinline__ float bfly_sum(float v) {
    #pragma unroll
    for (int o = 16; o; o >>= 1) v += __shfl_xor_sync(FULL, v, o);
    return v;
}

// ======================================================================
// P1: per-vocab encode (embed -> FF -> residual -> LN -> k/v/q tables)
// grid 64, block 128.
// ======================================================================
__global__ void precompute_tables(
    const float* __restrict__ embed, const float* __restrict__ W1,
    const float* __restrict__ b1, const float* __restrict__ W2,
    const float* __restrict__ b2, const float* __restrict__ gamma,
    const float* __restrict__ beta, const float* __restrict__ Wk,
    const float* __restrict__ Wv, const float* __restrict__ Wq)
{
    const int v = blockIdx.x, tid = threadIdx.x;
    __shared__ __align__(16) float e[H], f1[2 * H], h[H], hs[H];
    __shared__ float s_mu, s_rstd, s_kinv;

    if (tid < H) e[tid] = embed[v * H + tid];
    __syncthreads();

    {
        const float4* w4 = (const float4*)(W1 + tid * H);
        const float4* e4 = (const float4*)e;
        float a0 = 0.f, a1 = 0.f, a2 = 0.f, a3 = 0.f;
        #pragma unroll
        for (int i = 0; i < 16; i++) {
            float4 w = w4[i], ee = e4[i];
            a0 = fmaf(w.x, ee.x, a0); a1 = fmaf(w.y, ee.y, a1);
            a2 = fmaf(w.z, ee.z, a2); a3 = fmaf(w.w, ee.w, a3);
        }
        f1[tid] = fmaxf((a0 + a1) + (a2 + a3) + b1[tid], 0.0f);
    }
    __syncthreads();

    if (tid < H) {
        const float4* w4 = (const float4*)(W2 + tid * 2 * H);
        const float4* f4 = (const float4*)f1;
        float a0 = 0.f, a1 = 0.f, a2 = 0.f, a3 = 0.f;
        float b0 = 0.f, c1 = 0.f, c2 = 0.f, b3 = 0.f;
        #pragma unroll
        for (int i = 0; i < 32; i += 2) {
            float4 w = w4[i], ff = f4[i];
            a0 = fmaf(w.x, ff.x, a0); a1 = fmaf(w.y, ff.y, a1);
            a2 = fmaf(w.z, ff.z, a2); a3 = fmaf(w.w, ff.w, a3);
            float4 w2_ = w4[i + 1], ff2 = f4[i + 1];
            b0 = fmaf(w2_.x, ff2.x, b0); c1 = fmaf(w2_.y, ff2.y, c1);
            c2 = fmaf(w2_.z, ff2.z, c2); b3 = fmaf(w2_.w, ff2.w, b3);
        }
        h[tid] = e[tid] + ((a0 + a1) + (a2 + a3)) + ((b0 + c1) + (c2 + b3)) + b2[tid];
    }
    __syncthreads();

    if (tid < 32) {
        float x = bfly_sum(h[tid] + h[tid + 32]);
        float mu = x * (1.0f / H);
        float c0 = h[tid] - mu, c1_ = h[tid + 32] - mu;
        float vv = bfly_sum(c0 * c0 + c1_ * c1_);
        if (tid == 0) { s_mu = mu; s_rstd = rsqrtf(vv * (1.0f / H) + 1e-5f); }
    }
    __syncthreads();
    if (tid < H) hs[tid] = (h[tid] - s_mu) * s_rstd * gamma[tid] + beta[tid];
    __syncthreads();

    if (tid < H) {
        const float4* wk4 = (const float4*)(Wk + tid * H);
        const float4* wq4 = (const float4*)(Wq + tid * H);
        const float4* h4 = (const float4*)hs;
        float k0 = 0.f, k1 = 0.f, k2 = 0.f, k3 = 0.f;
        float q0 = 0.f, q1 = 0.f, q2 = 0.f, q3 = 0.f;
        #pragma unroll
        for (int i = 0; i < 16; i++) {
            float4 wk = wk4[i], wq = wq4[i], hh = h4[i];
            k0 = fmaf(wk.x, hh.x, k0); k1 = fmaf(wk.y, hh.y, k1);
            k2 = fmaf(wk.z, hh.z, k2); k3 = fmaf(wk.w, hh.w, k3);
            q0 = fmaf(wq.x, hh.x, q0); q1 = fmaf(wq.y, hh.y, q1);
            q2 = fmaf(wq.z, hh.z, q2); q3 = fmaf(wq.w, hh.w, q3);
        }
        h[tid] = (k0 + k1) + (k2 + k3);   // raw k
        g_qtab[v * H + tid] = (q0 + q1) + (q2 + q3);
    } else {
        const int i = tid - H;
        const float4* wv4 = (const float4*)(Wv + i * H);
        const float4* h4 = (const float4*)hs;
        float a0 = 0.f, a1 = 0.f, a2 = 0.f, a3 = 0.f;
        #pragma unroll
        for (int j = 0; j < 16; j++) {
            float4 w = wv4[j], hh = h4[j];
            a0 = fmaf(w.x, hh.x, a0); a1 = fmaf(w.y, hh.y, a1);
            a2 = fmaf(w.z, hh.z, a2); a3 = fmaf(w.w, hh.w, a3);
        }
        g_vtab[v * H + i] = (a0 + a1) + (a2 + a3);
    }
    __syncthreads();

    if (tid < 32) {
        float n = bfly_sum(h[tid] * h[tid] + h[tid + 32] * h[tid + 32]);
        if (tid == 0) s_kinv = 1.0f / fmaxf(sqrtf(n), 1e-12f);
    }
    __syncthreads();
    if (tid < H) g_ktab[v * H + tid] = h[tid] * s_kinv;
}

// ======================================================================
// P2: Gram matrix KK = ktab ktab^T ; Wcomb = Wout @ Wrp ; bcomb
// grid 64, block 64
// ======================================================================
__global__ void precompute_misc(
    const float* __restrict__ Wrp, const float* __restrict__ brp,
    const float* __restrict__ Wout, const float* __restrict__ bout)
{
    const int i = blockIdx.x, j = threadIdx.x;
    const float4* ki4 = (const float4*)(g_ktab + i * H);
    const float4* kj4 = (const float4*)(g_ktab + j * H);
    float a0 = 0.f, a1 = 0.f, a2 = 0.f, a3 = 0.f;
    float w = 0.f, w1 = 0.f;
    #pragma unroll
    for (int l = 0; l < 16; l++) {
        float4 ka = ki4[l], kb = kj4[l];
        a0 = fmaf(ka.x, kb.x, a0); a1 = fmaf(ka.y, kb.y, a1);
        a2 = fmaf(ka.z, kb.z, a2); a3 = fmaf(ka.w, kb.w, a3);
    }
    #pragma unroll
    for (int l = 0; l < H; l += 2) {
        w  = fmaf(Wout[i * H + l],     Wrp[l * H + j],       w);
        w1 = fmaf(Wout[i * H + l + 1], Wrp[(l + 1) * H + j], w1);
    }
    g_KK[i * H + j] = (a0 + a1) + (a2 + a3);
    g_Wcomb[i * H + j] = w + w1;
    if (j == 0) {
        float bb = bout[i], bb1 = 0.f;
        #pragma unroll
        for (int l = 0; l < H; l += 2) {
            bb  = fmaf(Wout[i * H + l],     brp[l],     bb);
            bb1 = fmaf(Wout[i * H + l + 1], brp[l + 1], bb1);
        }
        g_bcomb[i] = bb + bb1;
    }
}

// ======================================================================
// Scan: one warp per block, TWO batches interleaved per warp so the
// second stream fills the first stream's SHFL/LDS latency shadow.
// grid 128, block 32.
// ======================================================================
__global__ void __launch_bounds__(32) scan_kernel(
    const int* __restrict__ seq, float* __restrict__ out)
{
    __shared__ __align__(16) float sk[VOCAB * H];          // 16 KB
    __shared__ __align__(16) float sv[VOCAB * H];          // 16 KB
    __shared__ __align__(16) float sKK[VOCAB * VOCAB];     // 16 KB
    __shared__ __align__(16) unsigned char sseq[2][LL];    // 4 KB
    __shared__ float smq[2][H];

    const int lane = threadIdx.x;
    const int b0 = blockIdx.x * 2;

    // stage tables + packed sequences
    {
        const float4* kg = (const float4*)g_ktab;
        const float4* vg = (const float4*)g_vtab;
        const float4* gg = (const float4*)g_KK;
        float4* ksh = (float4*)sk;
        float4* vsh = (float4*)sv;
        float4* gsh = (float4*)sKK;
        #pragma unroll
        for (int i = lane; i < VOCAB * H / 4; i += 32) {
            ksh[i] = kg[i]; vsh[i] = vg[i]; gsh[i] = gg[i];
        }
        #pragma unroll
        for (int c = 0; c < 2; c++) {
            const int4* sg = (const int4*)(seq + (b0 + c) * LL);
            uchar4* ssh = (uchar4*)sseq[c];
            for (int i = lane; i < LL / 4; i += 32) {
                int4 t = sg[i];
                ssh[i] = make_uchar4((unsigned char)t.x, (unsigned char)t.y,
                                     (unsigned char)t.z, (unsigned char)t.w);
            }
        }
    }
    __syncwarp();

    float2 p[2], acc[2];
    #pragma unroll
    for (int c = 0; c < 2; c++) {
        acc[c].x = 0.f; acc[c].y = 0.f;
        const int qi = sseq[c][LL - 1];
        p[c] = __ldg((const float2*)&g_qtab[qi * H + 2 * lane]);
    }

    // ---- 7 single steps per batch, interleaved ----
    #pragma unroll
    for (int t = LL - 2; t >= LL - 8; --t) {
        float s[2]; float2 k[2]; int idx[2];
        #pragma unroll
        for (int c = 0; c < 2; c++) {
            idx[c] = (int)sseq[c][t];
            k[c] = *(const float2*)&sk[idx[c] * H + 2 * lane];
            s[c] = fmaf(k[c].y, p[c].y, k[c].x * p[c].x);
        }
        #pragma unroll
        for (int o = 16; o; o >>= 1)
            #pragma unroll
            for (int c = 0; c < 2; c++) s[c] += __shfl_xor_sync(FULL, s[c], o);
        #pragma unroll
        for (int c = 0; c < 2; c++) {
            const float2 vv = *(const float2*)&sv[idx[c] * H + 2 * lane];
            acc[c].x = fmaf(s[c], vv.x, acc[c].x);
            acc[c].y = fmaf(s[c], vv.y, acc[c].y);
            p[c].x = fmaf(-s[c], k[c].x, p[c].x);
            p[c].y = fmaf(-s[c], k[c].y, p[c].y);
        }
    }

    const bool lo16 = (lane < 16);
    const bool lo8  = ((lane & 8) == 0);
    const bool lo4  = ((lane & 4) == 0);

    // ---- 255 groups of 8 per batch, fully interleaved ----
    for (int base = LL - 16; base >= 0; base -= 8) {
        int off[2][8];
        #pragma unroll
        for (int c = 0; c < 2; c++)
            #pragma unroll
            for (int j = 0; j < 8; j++)
                off[c][j] = ((int)sseq[c][base + 7 - j]) << 6;

        float2 kk[2][8];
        #pragma unroll
        for (int c = 0; c < 2; c++)
            #pragma unroll
            for (int j = 0; j < 8; j++)
                kk[c][j] = *(const float2*)&sk[off[c][j] + 2 * lane];

        // per-lane dot partials
        float d[2][8];
        #pragma unroll
        for (int c = 0; c < 2; c++)
            #pragma unroll
            for (int j = 0; j < 8; j++)
                d[c][j] = fmaf(kk[c][j].y, p[c].y, kk[c][j].x * p[c].x);

        // Gram gathers (issued before the trees; land in their shadow)
        float G[2][28];
        #pragma unroll
        for (int c = 0; c < 2; c++)
            #pragma unroll
            for (int j = 1; j < 8; j++)
                #pragma unroll
                for (int m = 0; m < j; m++)
                    G[c][j * (j - 1) / 2 + m] = sKK[off[c][j] + (off[c][m] >> 6)];

        // merged reduce-and-concentrate trees, stages interleaved A/B
        float m0[2], m1[2], m2[2], m3[2], n0[2], n1[2], r[2];
        #pragma unroll
        for (int c = 0; c < 2; c++)
            #pragma unroll
            for (int j = 0; j < 8; j++) d[c][j] += __shfl_xor_sync(FULL, d[c][j], 16);
        #pragma unroll
        for (int c = 0; c < 2; c++) {
            m0[c] = lo16 ? d[c][0] : d[c][1];
            m1[c] = lo16 ? d[c][2] : d[c][3];
            m2[c] = lo16 ? d[c][4] : d[c][5];
            m3[c] = lo16 ? d[c][6] : d[c][7];
        }
        #pragma unroll
        for (int c = 0; c < 2; c++) {
            m0[c] += __shfl_xor_sync(FULL, m0[c], 8);
            m1[c] += __shfl_xor_sync(FULL, m1[c], 8);
            m2[c] += __shfl_xor_sync(FULL, m2[c], 8);
            m3[c] += __shfl_xor_sync(FULL, m3[c], 8);
        }
        #pragma unroll
        for (int c = 0; c < 2; c++) {
            n0[c] = lo8 ? m0[c] : m1[c];
            n1[c] = lo8 ? m2[c] : m3[c];
        }
        #pragma unroll
        for (int c = 0; c < 2; c++) {
            n0[c] += __shfl_xor_sync(FULL, n0[c], 4);
            n1[c] += __shfl_xor_sync(FULL, n1[c], 4);
        }
        #pragma unroll
        for (int c = 0; c < 2; c++) r[c] = lo4 ? n0[c] : n1[c];
        #pragma unroll
        for (int c = 0; c < 2; c++) r[c] += __shfl_xor_sync(FULL, r[c], 2);
        #pragma unroll
        for (int c = 0; c < 2; c++) r[c] += __shfl_xor_sync(FULL, r[c], 1);

        float dt[2][8];
        #pragma unroll
        for (int c = 0; c < 2; c++) {
            dt[c][0] = __shfl_sync(FULL, r[c], 0);
            dt[c][1] = __shfl_sync(FULL, r[c], 16);
            dt[c][2] = __shfl_sync(FULL, r[c], 8);
            dt[c][3] = __shfl_sync(FULL, r[c], 24);
            dt[c][4] = __shfl_sync(FULL, r[c], 4);
            dt[c][5] = __shfl_sync(FULL, r[c], 20);
            dt[c][6] = __shfl_sync(FULL, r[c], 12);
            dt[c][7] = __shfl_sync(FULL, r[c], 28);
        }

        // forward substitution (serial chain per batch, interleaved)
        float s[2][8];
        #pragma unroll
        for (int c = 0; c < 2; c++)
            #pragma unroll
            for (int j = 0; j < 8; j++) {
                float a = dt[c][j];
                #pragma unroll
                for (int m = 0; m < j; m++)
                    a = fmaf(-G[c][j * (j - 1) / 2 + m], s[c][m], a);
                s[c][j] = a;
            }

        // p update via shallow pairwise delta tree
        #pragma unroll
        for (int c = 0; c < 2; c++) {
            float dx0 = fmaf(s[c][1], kk[c][1].x, s[c][0] * kk[c][0].x);
            float dx1 = fmaf(s[c][3], kk[c][3].x, s[c][2] * kk[c][2].x);
            float dx2 = fmaf(s[c][5], kk[c][5].x, s[c][4] * kk[c][4].x);
            float dx3 = fmaf(s[c][7], kk[c][7].x, s[c][6] * kk[c][6].x);
            float dy0 = fmaf(s[c][1], kk[c][1].y, s[c][0] * kk[c][0].y);
            float dy1 = fmaf(s[c][3], kk[c][3].y, s[c][2] * kk[c][2].y);
            float dy2 = fmaf(s[c][5], kk[c][5].y, s[c][4] * kk[c][4].y);
            float dy3 = fmaf(s[c][7], kk[c][7].y, s[c][6] * kk[c][6].y);
            p[c].x -= (dx0 + dx1) + (dx2 + dx3);
            p[c].y -= (dy0 + dy1) + (dy2 + dy3);
        }

        // Mq accumulation from smem (off critical path)
        #pragma unroll
        for (int c = 0; c < 2; c++)
            #pragma unroll
            for (int j = 0; j < 8; j++) {
                const float2 vv = *(const float2*)&sv[off[c][j] + 2 * lane];
                acc[c].x = fmaf(s[c][j], vv.x, acc[c].x);
                acc[c].y = fmaf(s[c][j], vv.y, acc[c].y);
            }
    }

    // ---- epilogue: out = Wcomb @ (Mq) + bcomb, both batches ----
    #pragma unroll
    for (int c = 0; c < 2; c++) {
        smq[c][2 * lane]     = acc[c].x;
        smq[c][2 * lane + 1] = acc[c].y;
    }
    __syncwarp();
    #pragma unroll
    for (int c = 0; c < 2; c++)
        #pragma unroll
        for (int rr = 0; rr < 2; rr++) {
            const int i = lane + 32 * rr;
            const float4* w4 = (const float4*)(g_Wcomb + i * H);
            const float4* m4 = (const float4*)smq[c];
            float a0 = 0.f, a1 = 0.f, a2 = 0.f, a3 = 0.f;
            #pragma unroll
            for (int j = 0; j < 16; j++) {
                float4 w = w4[j], m = m4[j];
                a0 = fmaf(w.x, m.x, a0); a1 = fmaf(w.y, m.y, a1);
                a2 = fmaf(w.z, m.z, a2); a3 = fmaf(w.w, m.w, a3);
            }
            out[(b0 + c) * H + i] = (a0 + a1) + (a2 + a3) + g_bcomb[i];
        }
}

// ======================================================================
extern "C" void kernel_launch(void* const* d_in, const int* in_sizes, int n_in,
                              void* d_out, int out_size)
{
    (void)in_sizes; (void)n_in; (void)out_size;
    const int*   seq   = (const int*)  d_in[0];
    const float* embed = (const float*)d_in[1];
    const float* W1    = (const float*)d_in[2];
    const float* b1    = (const float*)d_in[3];
    const float* W2    = (const float*)d_in[4];
    const float* b2    = (const float*)d_in[5];
    const float* gamma = (const float*)d_in[6];
    const float* beta  = (const float*)d_in[7];
    const float* Wk    = (const float*)d_in[8];
    const float* Wv    = (const float*)d_in[9];
    const float* Wq    = (const float*)d_in[10];
    const float* Wrp   = (const float*)d_in[11];
    const float* brp   = (const float*)d_in[12];
    const float* Wout  = (const float*)d_in[13];
    const float* bout  = (const float*)d_in[14];

    precompute_tables<<<VOCAB, 128>>>(embed, W1, b1, W2, b2, gamma, beta, Wk, Wv, Wq);
    precompute_misc<<<VOCAB, H>>>(Wrp, brp, Wout, bout);
    scan_kernel<<<NBLK, 32>>>(seq, (float*)d_out);
}

// round 5
// speedup vs baseline: 2.6060x; 2.6060x over previous
#include <cuda_runtime.h>

#define H  64
#define LL 2048
#define NB 256
#define VOCAB 64
#define FULL 0xffffffffu

// -------- device-global scratch (no runtime allocation allowed) --------
__device__ __align__(16) float g_ktab[VOCAB * H];   // normalized k per vocab id
__device__ __align__(16) float g_vtab[VOCAB * H];   // v per vocab id
__device__ __align__(16) float g_qtab[VOCAB * H];   // q per vocab id
__device__ __align__(16) float g_KK[VOCAB * VOCAB]; // Gram of normalized k table
__device__ __align__(16) float g_Wcomb[H * H];      // Wout @ Wrp
__device__ __align__(16) float g_bcomb[H];          // Wout @ brp + bout

__device__ __forceinline__ float bfly_sum(float v) {
    #pragma unroll
    for (int o = 16; o; o >>= 1) v += __shfl_xor_sync(FULL, v, o);
    return v;
}

// ======================================================================
// P1: per-vocab encode (embed -> FF -> residual -> LN -> k/v/q tables)
// grid 64, block 128.  (unchanged from R3 — proven)
// ======================================================================
__global__ void precompute_tables(
    const float* __restrict__ embed, const float* __restrict__ W1,
    const float* __restrict__ b1, const float* __restrict__ W2,
    const float* __restrict__ b2, const float* __restrict__ gamma,
    const float* __restrict__ beta, const float* __restrict__ Wk,
    const float* __restrict__ Wv, const float* __restrict__ Wq)
{
    const int v = blockIdx.x, tid = threadIdx.x;
    __shared__ __align__(16) float e[H], f1[2 * H], h[H], hs[H];
    __shared__ float s_mu, s_rstd, s_kinv;

    if (tid < H) e[tid] = embed[v * H + tid];
    __syncthreads();

    {
        const float4* w4 = (const float4*)(W1 + tid * H);
        const float4* e4 = (const float4*)e;
        float a0 = 0.f, a1 = 0.f, a2 = 0.f, a3 = 0.f;
        #pragma unroll
        for (int i = 0; i < 16; i++) {
            float4 w = w4[i], ee = e4[i];
            a0 = fmaf(w.x, ee.x, a0); a1 = fmaf(w.y, ee.y, a1);
            a2 = fmaf(w.z, ee.z, a2); a3 = fmaf(w.w, ee.w, a3);
        }
        f1[tid] = fmaxf((a0 + a1) + (a2 + a3) + b1[tid], 0.0f);
    }
    __syncthreads();

    if (tid < H) {
        const float4* w4 = (const float4*)(W2 + tid * 2 * H);
        const float4* f4 = (const float4*)f1;
        float a0 = 0.f, a1 = 0.f, a2 = 0.f, a3 = 0.f;
        float b0 = 0.f, c1 = 0.f, c2 = 0.f, b3 = 0.f;
        #pragma unroll
        for (int i = 0; i < 32; i += 2) {
            float4 w = w4[i], ff = f4[i];
            a0 = fmaf(w.x, ff.x, a0); a1 = fmaf(w.y, ff.y, a1);
            a2 = fmaf(w.z, ff.z, a2); a3 = fmaf(w.w, ff.w, a3);
            float4 w2_ = w4[i + 1], ff2 = f4[i + 1];
            b0 = fmaf(w2_.x, ff2.x, b0); c1 = fmaf(w2_.y, ff2.y, c1);
            c2 = fmaf(w2_.z, ff2.z, c2); b3 = fmaf(w2_.w, ff2.w, b3);
        }
        h[tid] = e[tid] + ((a0 + a1) + (a2 + a3)) + ((b0 + c1) + (c2 + b3)) + b2[tid];
    }
    __syncthreads();

    if (tid < 32) {
        float x = bfly_sum(h[tid] + h[tid + 32]);
        float mu = x * (1.0f / H);
        float c0 = h[tid] - mu, c1_ = h[tid + 32] - mu;
        float vv = bfly_sum(c0 * c0 + c1_ * c1_);
        if (tid == 0) { s_mu = mu; s_rstd = rsqrtf(vv * (1.0f / H) + 1e-5f); }
    }
    __syncthreads();
    if (tid < H) hs[tid] = (h[tid] - s_mu) * s_rstd * gamma[tid] + beta[tid];
    __syncthreads();

    if (tid < H) {
        const float4* wk4 = (const float4*)(Wk + tid * H);
        const float4* wq4 = (const float4*)(Wq + tid * H);
        const float4* h4 = (const float4*)hs;
        float k0 = 0.f, k1 = 0.f, k2 = 0.f, k3 = 0.f;
        float q0 = 0.f, q1 = 0.f, q2 = 0.f, q3 = 0.f;
        #pragma unroll
        for (int i = 0; i < 16; i++) {
            float4 wk = wk4[i], wq = wq4[i], hh = h4[i];
            k0 = fmaf(wk.x, hh.x, k0); k1 = fmaf(wk.y, hh.y, k1);
            k2 = fmaf(wk.z, hh.z, k2); k3 = fmaf(wk.w, hh.w, k3);
            q0 = fmaf(wq.x, hh.x, q0); q1 = fmaf(wq.y, hh.y, q1);
            q2 = fmaf(wq.z, hh.z, q2); q3 = fmaf(wq.w, hh.w, q3);
        }
        h[tid] = (k0 + k1) + (k2 + k3);   // raw k
        g_qtab[v * H + tid] = (q0 + q1) + (q2 + q3);
    } else {
        const int i = tid - H;
        const float4* wv4 = (const float4*)(Wv + i * H);
        const float4* h4 = (const float4*)hs;
        float a0 = 0.f, a1 = 0.f, a2 = 0.f, a3 = 0.f;
        #pragma unroll
        for (int j = 0; j < 16; j++) {
            float4 w = wv4[j], hh = h4[j];
            a0 = fmaf(w.x, hh.x, a0); a1 = fmaf(w.y, hh.y, a1);
            a2 = fmaf(w.z, hh.z, a2); a3 = fmaf(w.w, hh.w, a3);
        }
        g_vtab[v * H + i] = (a0 + a1) + (a2 + a3);
    }
    __syncthreads();

    if (tid < 32) {
        float n = bfly_sum(h[tid] * h[tid] + h[tid + 32] * h[tid + 32]);
        if (tid == 0) s_kinv = 1.0f / fmaxf(sqrtf(n), 1e-12f);
    }
    __syncthreads();
    if (tid < H) g_ktab[v * H + tid] = h[tid] * s_kinv;
}

// ======================================================================
// P2: Gram matrix KK = ktab ktab^T ; Wcomb = Wout @ Wrp ; bcomb
// grid 64, block 64
// ======================================================================
__global__ void precompute_misc(
    const float* __restrict__ Wrp, const float* __restrict__ brp,
    const float* __restrict__ Wout, const float* __restrict__ bout)
{
    const int i = blockIdx.x, j = threadIdx.x;
    const float4* ki4 = (const float4*)(g_ktab + i * H);
    const float4* kj4 = (const float4*)(g_ktab + j * H);
    float a0 = 0.f, a1 = 0.f, a2 = 0.f, a3 = 0.f;
    float w = 0.f, w1 = 0.f;
    #pragma unroll
    for (int l = 0; l < 16; l++) {
        float4 ka = ki4[l], kb = kj4[l];
        a0 = fmaf(ka.x, kb.x, a0); a1 = fmaf(ka.y, kb.y, a1);
        a2 = fmaf(ka.z, kb.z, a2); a3 = fmaf(ka.w, kb.w, a3);
    }
    #pragma unroll
    for (int l = 0; l < H; l += 2) {
        w  = fmaf(Wout[i * H + l],     Wrp[l * H + j],       w);
        w1 = fmaf(Wout[i * H + l + 1], Wrp[(l + 1) * H + j], w1);
    }
    g_KK[i * H + j] = (a0 + a1) + (a2 + a3);
    g_Wcomb[i * H + j] = w + w1;
    if (j == 0) {
        float bb = bout[i], bb1 = 0.f;
        #pragma unroll
        for (int l = 0; l < H; l += 2) {
            bb  = fmaf(Wout[i * H + l],     brp[l],     bb);
            bb1 = fmaf(Wout[i * H + l + 1], brp[l + 1], bb1);
        }
        g_bcomb[i] = bb + bb1;
    }
}

// ======================================================================
// Scan (scalarized): per batch maintain R[64] = Kq - KK@S spread 2/lane.
// s_t = R[id_t] fetched by one SEL+SHFL; R and Mq updated by one smem row
// each. Chunked C=4 with tiny Gram substitution (6 entries).
// grid 64, block 128 (4 warps = 4 batches; tables staged once per block).
// ======================================================================
__global__ void __launch_bounds__(128) scan_kernel(
    const int* __restrict__ seq, float* __restrict__ out)
{
    __shared__ __align__(16) float sKKn[VOCAB * H];        // 16 KB  (NEGATED KK)
    __shared__ __align__(16) float svt[VOCAB * H];         // 16 KB  (vtab)
    __shared__ __align__(16) unsigned char sseq[4][LL];    // 8 KB
    __shared__ __align__(16) float smq[4][H];              // 1 KB

    const int tid  = threadIdx.x;
    const int lane = tid & 31;
    const int w    = tid >> 5;
    const int b    = blockIdx.x * 4 + w;

    // ---- stage tables (cooperative, 128 threads) ----
    {
        const float4* kg = (const float4*)g_KK;
        const float4* vg = (const float4*)g_vtab;
        float4* ks = (float4*)sKKn;
        float4* vs = (float4*)svt;
        #pragma unroll
        for (int i = tid; i < VOCAB * H / 4; i += 128) {
            float4 a = kg[i];
            ks[i] = make_float4(-a.x, -a.y, -a.z, -a.w);
            vs[i] = vg[i];
        }
        // each warp stages its own sequence, packed to bytes
        const int4* sg = (const int4*)(seq + b * LL);
        uchar4* ssh = (uchar4*)sseq[w];
        for (int i = lane; i < LL / 4; i += 32) {
            int4 t = sg[i];
            ssh[i] = make_uchar4((unsigned char)t.x, (unsigned char)t.y,
                                 (unsigned char)t.z, (unsigned char)t.w);
        }
    }
    __syncthreads();

    const unsigned char* myseq = sseq[w];

    // ---- init: R_v = ktab[v] . q  for v = 2*lane, 2*lane+1 ----
    float Rx = 0.f, Ry = 0.f;
    {
        const int qid = myseq[LL - 1];
        const float4* q4 = (const float4*)(g_qtab + qid * H);
        const float4* ka = (const float4*)(g_ktab + (2 * lane) * H);
        const float4* kb = (const float4*)(g_ktab + (2 * lane + 1) * H);
        float x0 = 0.f, x1 = 0.f, y0 = 0.f, y1 = 0.f;
        #pragma unroll
        for (int i = 0; i < 16; i += 2) {
            float4 q0 = __ldg(q4 + i),  a0 = __ldg(ka + i),  b0 = __ldg(kb + i);
            float4 q1 = __ldg(q4 + i + 1), a1 = __ldg(ka + i + 1), b1 = __ldg(kb + i + 1);
            x0 = fmaf(a0.x, q0.x, x0); x0 = fmaf(a0.y, q0.y, x0);
            x0 = fmaf(a0.z, q0.z, x0); x0 = fmaf(a0.w, q0.w, x0);
            x1 = fmaf(a1.x, q1.x, x1); x1 = fmaf(a1.y, q1.y, x1);
            x1 = fmaf(a1.z, q1.z, x1); x1 = fmaf(a1.w, q1.w, x1);
            y0 = fmaf(b0.x, q0.x, y0); y0 = fmaf(b0.y, q0.y, y0);
            y0 = fmaf(b0.z, q0.z, y0); y0 = fmaf(b0.w, q0.w, y0);
            y1 = fmaf(b1.x, q1.x, y1); y1 = fmaf(b1.y, q1.y, y1);
            y1 = fmaf(b1.z, q1.z, y1); y1 = fmaf(b1.w, q1.w, y1);
        }
        Rx = x0 + x1; Ry = y0 + y1;
    }

    float ax = 0.f, ay = 0.f;   // Mq accumulator (2 elems/lane)
    const int lo2 = 2 * lane;

    // ---- 3 single steps: t = 2046, 2045, 2044 ----
    #pragma unroll
    for (int t = LL - 2; t >= LL - 4; --t) {
        const int id = (int)myseq[t];
        float tmp = (id & 1) ? Ry : Rx;
        float s = __shfl_sync(FULL, tmp, id >> 1);
        const float2 kr = *(const float2*)&sKKn[id * H + lo2];
        const float2 vr = *(const float2*)&svt[id * H + lo2];
        Rx = fmaf(kr.x, s, Rx);  Ry = fmaf(kr.y, s, Ry);
        ax = fmaf(vr.x, s, ax);  ay = fmaf(vr.y, s, ay);
    }

    // ---- 511 groups of 4: t in [base, base+3], j=0 is largest t ----
    #pragma unroll 2
    for (int base = LL - 8; base >= 0; base -= 4) {
        const unsigned int ids = *(const unsigned int*)(myseq + base);
        const int id0 = (int)(ids >> 24);          // t = base+3
        const int id1 = (int)((ids >> 16) & 0xff); // t = base+2
        const int id2 = (int)((ids >> 8) & 0xff);  // t = base+1
        const int id3 = (int)(ids & 0xff);         // t = base

        const int r0 = id0 * H, r1 = id1 * H, r2 = id2 * H, r3 = id3 * H;

        // Gram entries (negated): G'[j][m] = -KK[id_j][id_m], m<j
        const float gn10 = sKKn[r1 + id0];
        const float gn20 = sKKn[r2 + id0];
        const float gn21 = sKKn[r2 + id1];
        const float gn30 = sKKn[r3 + id0];
        const float gn31 = sKKn[r3 + id1];
        const float gn32 = sKKn[r3 + id2];

        // rows for R / Mq updates (issued early; independent of R)
        const float2 k0 = *(const float2*)&sKKn[r0 + lo2];
        const float2 k1 = *(const float2*)&sKKn[r1 + lo2];
        const float2 k2 = *(const float2*)&sKKn[r2 + lo2];
        const float2 k3 = *(const float2*)&sKKn[r3 + lo2];
        const float2 v0 = *(const float2*)&svt[r0 + lo2];
        const float2 v1 = *(const float2*)&svt[r1 + lo2];
        const float2 v2 = *(const float2*)&svt[r2 + lo2];
        const float2 v3 = *(const float2*)&svt[r3 + lo2];

        // fetch d_j = R[id_j] (group-start value) via SEL + SHFL
        float t0 = (id0 & 1) ? Ry : Rx;
        float t1 = (id1 & 1) ? Ry : Rx;
        float t2 = (id2 & 1) ? Ry : Rx;
        float t3 = (id3 & 1) ? Ry : Rx;
        const float d0 = __shfl_sync(FULL, t0, id0 >> 1);
        const float d1 = __shfl_sync(FULL, t1, id1 >> 1);
        const float d2 = __shfl_sync(FULL, t2, id2 >> 1);
        const float d3 = __shfl_sync(FULL, t3, id3 >> 1);

        // forward substitution with negated Gram (FMA with +)
        const float s0 = d0;
        const float s1 = fmaf(gn10, s0, d1);
        const float s2 = fmaf(gn21, s1, fmaf(gn20, s0, d2));
        const float s3 = fmaf(gn32, s2, fmaf(gn31, s1, fmaf(gn30, s0, d3)));

        // R += (-KK row_j) * s_j   (critical path into next group)
        Rx = fmaf(k0.x, s0, Rx);  Ry = fmaf(k0.y, s0, Ry);
        Rx = fmaf(k1.x, s1, Rx);  Ry = fmaf(k1.y, s1, Ry);
        Rx = fmaf(k2.x, s2, Rx);  Ry = fmaf(k2.y, s2, Ry);
        Rx = fmaf(k3.x, s3, Rx);  Ry = fmaf(k3.y, s3, Ry);

        // Mq += vtab row_j * s_j  (off critical path)
        ax = fmaf(v0.x, s0, ax);  ay = fmaf(v0.y, s0, ay);
        ax = fmaf(v1.x, s1, ax);  ay = fmaf(v1.y, s1, ay);
        ax = fmaf(v2.x, s2, ax);  ay = fmaf(v2.y, s2, ay);
        ax = fmaf(v3.x, s3, ax);  ay = fmaf(v3.y, s3, ay);
    }

    // ---- epilogue: out = Wcomb @ Mq + bcomb ----
    smq[w][lo2]     = ax;
    smq[w][lo2 + 1] = ay;
    __syncwarp();
    #pragma unroll
    for (int rr = 0; rr < 2; rr++) {
        const int i = lane + 32 * rr;
        const float4* w4 = (const float4*)(g_Wcomb + i * H);
        const float4* m4 = (const float4*)smq[w];
        float a0 = 0.f, a1 = 0.f, a2 = 0.f, a3 = 0.f;
        #pragma unroll
        for (int j = 0; j < 16; j++) {
            float4 ww = __ldg(w4 + j);
            float4 m = m4[j];
            a0 = fmaf(ww.x, m.x, a0); a1 = fmaf(ww.y, m.y, a1);
            a2 = fmaf(ww.z, m.z, a2); a3 = fmaf(ww.w, m.w, a3);
        }
        out[b * H + i] = (a0 + a1) + (a2 + a3) + g_bcomb[i];
    }
}

// ======================================================================
extern "C" void kernel_launch(void* const* d_in, const int* in_sizes, int n_in,
                              void* d_out, int out_size)
{
    (void)in_sizes; (void)n_in; (void)out_size;
    const int*   seq   = (const int*)  d_in[0];
    const float* embed = (const float*)d_in[1];
    const float* W1    = (const float*)d_in[2];
    const float* b1    = (const float*)d_in[3];
    const float* W2    = (const float*)d_in[4];
    const float* b2    = (const float*)d_in[5];
    const float* gamma = (const float*)d_in[6];
    const float* beta  = (const float*)d_in[7];
    const float* Wk    = (const float*)d_in[8];
    const float* Wv    = (const float*)d_in[9];
    const float* Wq    = (const float*)d_in[10];
    const float* Wrp   = (const float*)d_in[11];
    const float* brp   = (const float*)d_in[12];
    const float* Wout  = (const float*)d_in[13];
    const float* bout  = (const float*)d_in[14];

    precompute_tables<<<VOCAB, 128>>>(embed, W1, b1, W2, b2, gamma, beta, Wk, Wv, Wq);
    precompute_misc<<<VOCAB, H>>>(Wrp, brp, Wout, bout);
    scan_kernel<<<64, 128>>>(seq, (float*)d_out);
}

// round 6
// speedup vs baseline: 2.7623x; 1.0600x over previous
#include <cuda_runtime.h>

#define H  64
#define LL 2048
#define VOCAB 64
#define FULL 0xffffffffu

// -------- device-global scratch (no runtime allocation allowed) --------
__device__ __align__(16) float g_ktab[VOCAB * H];    // normalized k per vocab id
__device__ __align__(16) float g_vtab[VOCAB * H];    // v per vocab id
__device__ __align__(16) float g_qtab[VOCAB * H];    // q per vocab id
__device__ __align__(16) float g_KKn[VOCAB * VOCAB]; // NEGATED Gram of k table
__device__ __align__(16) float g_Wcomb[H * H];       // Wout @ Wrp
__device__ __align__(16) float g_bcomb[H];           // Wout @ brp + bout
__device__ unsigned g_bar1 = 0, g_bar2 = 0, g_rst = 0;   // spin barriers

__device__ __forceinline__ float bfly_sum(float v) {
    #pragma unroll
    for (int o = 16; o; o >>= 1) v += __shfl_xor_sync(FULL, v, o);
    return v;
}

// ======================================================================
// Single fused kernel. grid 64, block 128.
//   Phase A: block v encodes vocab v (tables) + Wcomb row v; warps stage
//            their batch sequences.           -> barrier 1
//   Phase B: block v computes negated KK row v; R-init overlapped with
//            barrier-2 arrive/wait.           -> barrier 2
//   Phase C: stage KKn to smem; 4 warps scan 4 batches (scalarized
//            recurrence, C=4 Gram chunks, per-vocab S scatter); epilogue.
// ======================================================================
__global__ void __launch_bounds__(128) fused_kernel(
    const int*   __restrict__ seq,
    const float* __restrict__ embed, const float* __restrict__ W1,
    const float* __restrict__ b1, const float* __restrict__ W2,
    const float* __restrict__ b2, const float* __restrict__ gamma,
    const float* __restrict__ beta, const float* __restrict__ Wk,
    const float* __restrict__ Wv, const float* __restrict__ Wq,
    const float* __restrict__ Wrp, const float* __restrict__ brp,
    const float* __restrict__ Wout, const float* __restrict__ bout,
    float* __restrict__ out)
{
    __shared__ __align__(16) float sKKn[VOCAB * H];        // 16 KB
    __shared__ __align__(16) unsigned char sseq[4][LL];    // 8 KB
    __shared__ __align__(16) float e[H], f1[2 * H], h[H], hs[H];
    __shared__ __align__(16) float sS[4][H];               // per-vocab s sums
    __shared__ __align__(16) float smq[4][H];
    __shared__ float s_mu, s_rstd, s_kinv;

    const int v    = blockIdx.x;
    const int tid  = threadIdx.x;
    const int lane = tid & 31;
    const int w    = tid >> 5;
    const int b    = v * 4 + w;
    const int lo2  = 2 * lane;

    // ---- stage this block's 4 sequences (independent of everything) ----
    {
        const int4* sg = (const int4*)(seq + b * LL);
        uchar4* ssh = (uchar4*)sseq[w];
        #pragma unroll 4
        for (int i = lane; i < LL / 4; i += 32) {
            int4 t = sg[i];
            ssh[i] = make_uchar4((unsigned char)t.x, (unsigned char)t.y,
                                 (unsigned char)t.z, (unsigned char)t.w);
        }
    }

    // ================= Phase A: encode vocab v =================
    if (tid < H) e[tid] = embed[v * H + tid];
    __syncthreads();

    {   // ff1 = relu(W1 e + b1)
        const float4* w4 = (const float4*)(W1 + tid * H);
        const float4* e4 = (const float4*)e;
        float a0 = 0.f, a1 = 0.f, a2 = 0.f, a3 = 0.f;
        #pragma unroll
        for (int i = 0; i < 16; i++) {
            float4 ww = w4[i], ee = e4[i];
            a0 = fmaf(ww.x, ee.x, a0); a1 = fmaf(ww.y, ee.y, a1);
            a2 = fmaf(ww.z, ee.z, a2); a3 = fmaf(ww.w, ee.w, a3);
        }
        f1[tid] = fmaxf((a0 + a1) + (a2 + a3) + b1[tid], 0.0f);
    }
    __syncthreads();

    if (tid < H) {   // h = e + W2 ff1 + b2
        const float4* w4 = (const float4*)(W2 + tid * 2 * H);
        const float4* f4 = (const float4*)f1;
        float a0 = 0.f, a1 = 0.f, a2 = 0.f, a3 = 0.f;
        float b0 = 0.f, c1 = 0.f, c2 = 0.f, b3 = 0.f;
        #pragma unroll
        for (int i = 0; i < 32; i += 2) {
            float4 ww = w4[i], ff = f4[i];
            a0 = fmaf(ww.x, ff.x, a0); a1 = fmaf(ww.y, ff.y, a1);
            a2 = fmaf(ww.z, ff.z, a2); a3 = fmaf(ww.w, ff.w, a3);
            float4 w2_ = w4[i + 1], ff2 = f4[i + 1];
            b0 = fmaf(w2_.x, ff2.x, b0); c1 = fmaf(w2_.y, ff2.y, c1);
            c2 = fmaf(w2_.z, ff2.z, c2); b3 = fmaf(w2_.w, ff2.w, b3);
        }
        h[tid] = e[tid] + ((a0 + a1) + (a2 + a3)) + ((b0 + c1) + (c2 + b3)) + b2[tid];
    }
    __syncthreads();

    if (tid < 32) {   // LayerNorm stats (biased var, eps 1e-5)
        float x = bfly_sum(h[tid] + h[tid + 32]);
        float mu = x * (1.0f / H);
        float c0 = h[tid] - mu, c1_ = h[tid + 32] - mu;
        float vv = bfly_sum(c0 * c0 + c1_ * c1_);
        if (tid == 0) { s_mu = mu; s_rstd = rsqrtf(vv * (1.0f / H) + 1e-5f); }
    }
    __syncthreads();
    if (tid < H) hs[tid] = (h[tid] - s_mu) * s_rstd * gamma[tid] + beta[tid];
    __syncthreads();

    if (tid < H) {   // k (raw) and q projections
        const float4* wk4 = (const float4*)(Wk + tid * H);
        const float4* wq4 = (const float4*)(Wq + tid * H);
        const float4* h4 = (const float4*)hs;
        float k0 = 0.f, k1 = 0.f, k2 = 0.f, k3 = 0.f;
        float q0 = 0.f, q1 = 0.f, q2 = 0.f, q3 = 0.f;
        #pragma unroll
        for (int i = 0; i < 16; i++) {
            float4 wk = wk4[i], wq = wq4[i], hh = h4[i];
            k0 = fmaf(wk.x, hh.x, k0); k1 = fmaf(wk.y, hh.y, k1);
            k2 = fmaf(wk.z, hh.z, k2); k3 = fmaf(wk.w, hh.w, k3);
            q0 = fmaf(wq.x, hh.x, q0); q1 = fmaf(wq.y, hh.y, q1);
            q2 = fmaf(wq.z, hh.z, q2); q3 = fmaf(wq.w, hh.w, q3);
        }
        h[tid] = (k0 + k1) + (k2 + k3);
        g_qtab[v * H + tid] = (q0 + q1) + (q2 + q3);
    } else {         // v projection
        const int i = tid - H;
        const float4* wv4 = (const float4*)(Wv + i * H);
        const float4* h4 = (const float4*)hs;
        float a0 = 0.f, a1 = 0.f, a2 = 0.f, a3 = 0.f;
        #pragma unroll
        for (int j = 0; j < 16; j++) {
            float4 ww = wv4[j], hh = h4[j];
            a0 = fmaf(ww.x, hh.x, a0); a1 = fmaf(ww.y, hh.y, a1);
            a2 = fmaf(ww.z, hh.z, a2); a3 = fmaf(ww.w, hh.w, a3);
        }
        g_vtab[v * H + i] = (a0 + a1) + (a2 + a3);
    }
    __syncthreads();

    if (tid < 32) {   // k normalization
        float n = bfly_sum(h[tid] * h[tid] + h[tid + 32] * h[tid + 32]);
        if (tid == 0) s_kinv = 1.0f / fmaxf(sqrtf(n), 1e-12f);
    }
    __syncthreads();
    if (tid < H) {
        float kv = h[tid] * s_kinv;
        g_ktab[v * H + tid] = kv;
        hs[tid] = kv;                 // keep own k row in smem for KK phase
    }

    // Wcomb row v + bcomb[v] (independent of tables)
    if (tid < H) {
        float ww = 0.f, w1_ = 0.f;
        #pragma unroll
        for (int l = 0; l < H; l += 2) {
            ww  = fmaf(Wout[v * H + l],     Wrp[l * H + tid],       ww);
            w1_ = fmaf(Wout[v * H + l + 1], Wrp[(l + 1) * H + tid], w1_);
        }
        g_Wcomb[v * H + tid] = ww + w1_;
    }
    if (tid == 0) {
        float bb = bout[v], bb1 = 0.f;
        #pragma unroll
        for (int l = 0; l < H; l += 2) {
            bb  = fmaf(Wout[v * H + l],     brp[l],     bb);
            bb1 = fmaf(Wout[v * H + l + 1], brp[l + 1], bb1);
        }
        g_bcomb[v] = bb + bb1;
    }

    // ---- barrier 1: all tables visible ----
    __syncthreads();
    if (tid == 0) {
        __threadfence();
        atomicAdd(&g_bar1, 1u);
        while (atomicAdd(&g_bar1, 0u) < 64u) { }
        __threadfence();
    }
    __syncthreads();

    // ================= Phase B: negated KK row v =================
    if (tid < H) {
        const int j = tid;
        const float4* kj4 = (const float4*)(g_ktab + j * H);
        const float4* ki4 = (const float4*)hs;
        float a0 = 0.f, a1 = 0.f, a2 = 0.f, a3 = 0.f;
        #pragma unroll
        for (int l = 0; l < 16; l++) {
            float4 ka = ki4[l], kb = __ldg(kj4 + l);
            a0 = fmaf(ka.x, kb.x, a0); a1 = fmaf(ka.y, kb.y, a1);
            a2 = fmaf(ka.z, kb.z, a2); a3 = fmaf(ka.w, kb.w, a3);
        }
        g_KKn[v * H + j] = -((a0 + a1) + (a2 + a3));
    }
    __syncthreads();
    if (tid == 0) { __threadfence(); atomicAdd(&g_bar2, 1u); }

    // ---- R-init per warp (needs only phase-A tables), hides bar2 wait ----
    float Rx = 0.f, Ry = 0.f;
    {
        const unsigned char* myseq = sseq[w];
        const int qid = myseq[LL - 1];
        const float4* q4 = (const float4*)(g_qtab + qid * H);
        const float4* ka = (const float4*)(g_ktab + lo2 * H);
        const float4* kb = (const float4*)(g_ktab + (lo2 + 1) * H);
        float x0 = 0.f, x1 = 0.f, y0 = 0.f, y1 = 0.f;
        #pragma unroll
        for (int i = 0; i < 16; i += 2) {
            float4 q0 = __ldg(q4 + i),     a0 = __ldg(ka + i),     b0 = __ldg(kb + i);
            float4 q1 = __ldg(q4 + i + 1), a1 = __ldg(ka + i + 1), b1 = __ldg(kb + i + 1);
            x0 = fmaf(a0.x, q0.x, x0); x0 = fmaf(a0.y, q0.y, x0);
            x0 = fmaf(a0.z, q0.z, x0); x0 = fmaf(a0.w, q0.w, x0);
            x1 = fmaf(a1.x, q1.x, x1); x1 = fmaf(a1.y, q1.y, x1);
            x1 = fmaf(a1.z, q1.z, x1); x1 = fmaf(a1.w, q1.w, x1);
            y0 = fmaf(b0.x, q0.x, y0); y0 = fmaf(b0.y, q0.y, y0);
            y0 = fmaf(b0.z, q0.z, y0); y0 = fmaf(b0.w, q0.w, y0);
            y1 = fmaf(b1.x, q1.x, y1); y1 = fmaf(b1.y, q1.y, y1);
            y1 = fmaf(b1.z, q1.z, y1); y1 = fmaf(b1.w, q1.w, y1);
        }
        Rx = x0 + x1; Ry = y0 + y1;
    }

    // ---- barrier 2 wait: all KK rows visible ----
    if (tid == 0) {
        while (atomicAdd(&g_bar2, 0u) < 64u) { }
        __threadfence();
    }
    __syncthreads();

    // ---- stage negated KK into smem (pure copy) ----
    {
        const float4* gg = (const float4*)g_KKn;
        float4* ks = (float4*)sKKn;
        #pragma unroll
        for (int i = tid; i < VOCAB * H / 4; i += 128) ks[i] = __ldg(gg + i);
    }
    __syncthreads();

    // ================= Phase C: scan (one warp = one batch) =================
    const unsigned char* myseq = sseq[w];
    float Sx = 0.f, Sy = 0.f;     // per-vocab s sums (2 vocab ids per lane)

    // 3 single steps: t = 2046, 2045, 2044
    #pragma unroll
    for (int t = LL - 2; t >= LL - 4; --t) {
        const int id = (int)myseq[t];
        float tmp = (id & 1) ? Ry : Rx;
        float s = __shfl_sync(FULL, tmp, id >> 1);
        const float2 kr = *(const float2*)&sKKn[id * H + lo2];
        Rx = fmaf(kr.x, s, Rx);  Ry = fmaf(kr.y, s, Ry);
        if (lane == (id >> 1)) { if (id & 1) Sy += s; else Sx += s; }
    }

    // 511 groups of 4
    #pragma unroll 2
    for (int base = LL - 8; base >= 0; base -= 4) {
        const unsigned int ids = *(const unsigned int*)(myseq + base);
        const int id0 = (int)(ids >> 24);          // t = base+3 (largest)
        const int id1 = (int)((ids >> 16) & 0xff);
        const int id2 = (int)((ids >> 8) & 0xff);
        const int id3 = (int)(ids & 0xff);

        const int r0 = id0 * H, r1 = id1 * H, r2 = id2 * H, r3 = id3 * H;

        // negated Gram entries
        const float gn10 = sKKn[r1 + id0];
        const float gn20 = sKKn[r2 + id0];
        const float gn21 = sKKn[r2 + id1];
        const float gn30 = sKKn[r3 + id0];
        const float gn31 = sKKn[r3 + id1];
        const float gn32 = sKKn[r3 + id2];

        // update rows (independent of R; issued early)
        const float2 k0 = *(const float2*)&sKKn[r0 + lo2];
        const float2 k1 = *(const float2*)&sKKn[r1 + lo2];
        const float2 k2 = *(const float2*)&sKKn[r2 + lo2];
        const float2 k3 = *(const float2*)&sKKn[r3 + lo2];

        // d_j = R[id_j] via SEL + SHFL
        float t0 = (id0 & 1) ? Ry : Rx;
        float t1 = (id1 & 1) ? Ry : Rx;
        float t2 = (id2 & 1) ? Ry : Rx;
        float t3 = (id3 & 1) ? Ry : Rx;
        const float d0 = __shfl_sync(FULL, t0, id0 >> 1);
        const float d1 = __shfl_sync(FULL, t1, id1 >> 1);
        const float d2 = __shfl_sync(FULL, t2, id2 >> 1);
        const float d3 = __shfl_sync(FULL, t3, id3 >> 1);

        // forward substitution (negated Gram -> pure FMA)
        const float s0 = d0;
        const float s1 = fmaf(gn10, s0, d1);
        const float s2 = fmaf(gn21, s1, fmaf(gn20, s0, d2));
        const float s3 = fmaf(gn32, s2, fmaf(gn31, s1, fmaf(gn30, s0, d3)));

        // R += (-KK row_j) * s_j (pairwise tree to shorten the chain)
        float dRx = fmaf(k1.x, s1, k0.x * s0) + fmaf(k3.x, s3, k2.x * s2);
        float dRy = fmaf(k1.y, s1, k0.y * s0) + fmaf(k3.y, s3, k2.y * s2);
        Rx += dRx; Ry += dRy;

        // per-vocab scatter: S[id_j] += s_j (owning lane only)
        if (lane == (id0 >> 1)) { if (id0 & 1) Sy += s0; else Sx += s0; }
        if (lane == (id1 >> 1)) { if (id1 & 1) Sy += s1; else Sx += s1; }
        if (lane == (id2 >> 1)) { if (id2 & 1) Sy += s2; else Sx += s2; }
        if (lane == (id3 >> 1)) { if (id3 & 1) Sy += s3; else Sx += s3; }
    }

    // ---- Mq = sum_v S_v * vtab[v]  (once per batch) ----
    sS[w][lo2] = Sx; sS[w][lo2 + 1] = Sy;
    __syncwarp();
    {
        float mx0 = 0.f, mx1 = 0.f, my0 = 0.f, my1 = 0.f;
        #pragma unroll 8
        for (int vv = 0; vv < VOCAB; vv += 2) {
            float sv0 = sS[w][vv], sv1 = sS[w][vv + 1];
            float2 vt0 = __ldg((const float2*)&g_vtab[vv * H + lo2]);
            float2 vt1 = __ldg((const float2*)&g_vtab[(vv + 1) * H + lo2]);
            mx0 = fmaf(sv0, vt0.x, mx0); my0 = fmaf(sv0, vt0.y, my0);
            mx1 = fmaf(sv1, vt1.x, mx1); my1 = fmaf(sv1, vt1.y, my1);
        }
        smq[w][lo2]     = mx0 + mx1;
        smq[w][lo2 + 1] = my0 + my1;
    }
    __syncwarp();

    // ---- epilogue: out = Wcomb @ Mq + bcomb ----
    #pragma unroll
    for (int rr = 0; rr < 2; rr++) {
        const int i = lane + 32 * rr;
        const float4* w4 = (const float4*)(g_Wcomb + i * H);
        const float4* m4 = (const float4*)smq[w];
        float a0 = 0.f, a1 = 0.f, a2 = 0.f, a3 = 0.f;
        #pragma unroll
        for (int j = 0; j < 16; j++) {
            float4 ww = __ldg(w4 + j);
            float4 m = m4[j];
            a0 = fmaf(ww.x, m.x, a0); a1 = fmaf(ww.y, m.y, a1);
            a2 = fmaf(ww.z, m.z, a2); a3 = fmaf(ww.w, m.w, a3);
        }
        out[b * H + i] = (a0 + a1) + (a2 + a3) + g_bcomb[i];
    }

    // ---- reset spin barriers for the next (graph-replayed) launch ----
    __syncthreads();
    if (tid == 0) {
        __threadfence();
        if (atomicAdd(&g_rst, 1u) == 63u) {
            atomicExch(&g_bar1, 0u);
            atomicExch(&g_bar2, 0u);
            atomicExch(&g_rst, 0u);
        }
    }
}

// ======================================================================
extern "C" void kernel_launch(void* const* d_in, const int* in_sizes, int n_in,
                              void* d_out, int out_size)
{
    (void)in_sizes; (void)n_in; (void)out_size;
    const int*   seq   = (const int*)  d_in[0];
    const float* embed = (const float*)d_in[1];
    const float* W1    = (const float*)d_in[2];
    const float* b1    = (const float*)d_in[3];
    const float* W2    = (const float*)d_in[4];
    const float* b2    = (const float*)d_in[5];
    const float* gamma = (const float*)d_in[6];
    const float* beta  = (const float*)d_in[7];
    const float* Wk    = (const float*)d_in[8];
    const float* Wv    = (const float*)d_in[9];
    const float* Wq    = (const float*)d_in[10];
    const float* Wrp   = (const float*)d_in[11];
    const float* brp   = (const float*)d_in[12];
    const float* Wout  = (const float*)d_in[13];
    const float* bout  = (const float*)d_in[14];

    fused_kernel<<<VOCAB, 128>>>(seq, embed, W1, b1, W2, b2, gamma, beta,
                                 Wk, Wv, Wq, Wrp, brp, Wout, bout,
                                 (float*)d_out);
}